// round 3
// baseline (speedup 1.0000x reference)
#include <cuda_runtime.h>
#include <math.h>

// ---------------- problem constants ----------------
#define B_     128
#define T_     64
#define EMB_   1536
#define ACT_   12
#define STOCH_ 32
#define DETER_ 1024
#define HID_   1024
#define OUTW_  1216   // 6*STOCH + DETER

// ---------------- persistent device state ----------------
__device__ float g_x[B_ * 2048];       // GRU input rows: [x(1024) | deter_m(1024)]
__device__ float g_P[B_ * 3072];       // GRU pre-norm output
__device__ float g_deter[B_ * DETER_];
__device__ float g_stoch[B_ * STOCH_];
__device__ float g_hs[B_ * HID_];      // img_out pre-norm
__device__ float g_xo[B_ * HID_];      // obs_out pre-norm
__device__ int   g_mode;               // 0=u8, 1=i32, 2=f32 for is_first

// ---------------- helpers ----------------
__device__ __forceinline__ float sigf(float x)  { return 1.f / (1.f + expf(-x)); }
__device__ __forceinline__ float splusf(float x){ return fmaxf(x, 0.f) + log1pf(expf(-fabsf(x))); }
__device__ __forceinline__ float eluf(float x)  { return x > 0.f ? x : expm1f(x); }
__device__ __forceinline__ float rstdf(float var){
    float a = var + 1e-5f;
    float r = rsqrtf(a);
    return r * (1.5f - 0.5f * a * r * r);   // one Newton step
}

__device__ __forceinline__ float get_mask(const void* isf, int row, int t){
    int e = row * T_ + t;
    int mode = g_mode;
    float f;
    if (mode == 0)      f = (float)((const unsigned char*)isf)[e];
    else if (mode == 1) f = (float)((const int*)isf)[e];
    else                f = ((const float*)isf)[e];
    return 1.f - f;
}

// block-wide (256 threads) sum of (a, b); sh must have >= 18 floats
__device__ __forceinline__ float2 blockred2(float a, float b, float* sh){
    #pragma unroll
    for (int o = 16; o; o >>= 1){
        a += __shfl_xor_sync(0xffffffffu, a, o);
        b += __shfl_xor_sync(0xffffffffu, b, o);
    }
    int w = threadIdx.x >> 5;
    if ((threadIdx.x & 31) == 0){ sh[w] = a; sh[8 + w] = b; }
    __syncthreads();
    if (threadIdx.x == 0){
        float sa = 0.f, sb = 0.f;
        #pragma unroll
        for (int i = 0; i < 8; i++){ sa += sh[i]; sb += sh[8 + i]; }
        sh[16] = sa; sh[17] = sb;
    }
    __syncthreads();
    return make_float2(sh[16], sh[17]);
}

// ---------------- dtype detector for is_first ----------------
// u8 bools -> bytes in {0,1} everywhere.
// i32 0/1  -> nonzero bytes only at positions %4==0, values 0/1.
// f32 0/1  -> bytes include 0x80, 0x3F.
__global__ void k_detect(const unsigned char* __restrict__ p){
    __shared__ int s[2];
    if (threadIdx.x < 2) s[threadIdx.x] = 0;
    __syncthreads();
    int f = 0, g = 0;
    for (int i = threadIdx.x; i < B_ * T_; i += blockDim.x){
        unsigned char b = p[i];
        if (b >= 2) f = 1;
        if (b == 1 && (i & 3)) g = 1;
    }
    if (f) atomicOr(&s[0], 1);
    if (g) atomicOr(&s[1], 1);
    __syncthreads();
    if (threadIdx.x == 0) g_mode = s[0] ? 2 : (s[1] ? 0 : 1);
}

// ---------------- k_pre: mask + img_in MLP + LN + elu -> g_x ----------------
__global__ void __launch_bounds__(256) k_pre(
    int t, const float* __restrict__ action, const void* __restrict__ isf,
    const float* __restrict__ Wii, const float* __restrict__ bii,
    const float* __restrict__ gii, const float* __restrict__ bnii)
{
    __shared__ float in44[44];
    __shared__ float red[18];
    int row = blockIdx.x, tid = threadIdx.x;
    float m = get_mask(isf, row, t);

    if (tid < 32)       in44[tid] = (t == 0 ? 0.f : g_stoch[row * STOCH_ + tid]) * m;
    else if (tid < 44)  in44[tid] = action[(row * T_ + t) * ACT_ + (tid - 32)] * m;
    __syncthreads();

    float acc[4];
    #pragma unroll
    for (int j = 0; j < 4; j++){
        int h = tid + 256 * j;
        float s = bii[h];
        #pragma unroll
        for (int k = 0; k < 44; k++) s = fmaf(in44[k], Wii[k * HID_ + h], s);
        acc[j] = s;
    }
    float s1 = 0.f, s2 = 0.f;
    #pragma unroll
    for (int j = 0; j < 4; j++){ s1 += acc[j]; s2 += acc[j] * acc[j]; }
    float2 r = blockred2(s1, s2, red);
    float mean = r.x * (1.f / 1024.f);
    float rstd = rstdf(r.y * (1.f / 1024.f) - mean * mean);

    #pragma unroll
    for (int j = 0; j < 4; j++){
        int h = tid + 256 * j;
        float xn = (acc[j] - mean) * rstd * gii[h] + bnii[h];
        g_x[row * 2048 + h] = eluf(xn);
        float dm = (t == 0 ? 0.f : g_deter[row * DETER_ + h]) * m;
        g_deter[row * DETER_ + h] = dm;          // masked old deter
        g_x[row * 2048 + 1024 + h] = dm;
    }
}

// ---------------- generic GEMM body: C[128 x NT-tile] = A @ W + bias ----------------
// A is virtual concat of A0 (K0 cols, stride lda0) and A1 (stride lda1). K % 32 == 0,
// K0 % 32 == 0. 128 threads: 16 row-groups x 8 col-groups; 8 rows x (NT/8) cols each.
template<int NT>
__device__ __forceinline__ void gemm_body(
    const float* __restrict__ A0, int K0, int lda0,
    const float* __restrict__ A1, int lda1, int K,
    const float* __restrict__ W, int ldw, const float* __restrict__ bias,
    float* __restrict__ C, int ldc, int col0)
{
    constexpr int CPT = NT / 8;
    __shared__ float As[128][36];
    __shared__ float Ws[32][NT];
    const int tid = threadIdx.x;
    const int rg = tid & 15, cg = tid >> 4;
    int rows[8];
    #pragma unroll
    for (int i = 0; i < 4; i++){ rows[i] = rg * 4 + i; rows[4 + i] = 64 + rg * 4 + i; }

    float acc[8][CPT];
    #pragma unroll
    for (int i = 0; i < 8; i++)
        #pragma unroll
        for (int c = 0; c < CPT; c++) acc[i][c] = 0.f;

    for (int kb = 0; kb < K; kb += 32){
        const float* Ap; int ld, kof;
        if (kb < K0){ Ap = A0; ld = lda0; kof = kb; }
        else        { Ap = A1; ld = lda1; kof = kb - K0; }
        __syncthreads();
        #pragma unroll
        for (int j = 0; j < 8; j++){
            int v = tid + 128 * j, rr = v >> 3, c4 = (v & 7) * 4;
            *(float4*)&As[rr][c4] = *(const float4*)(Ap + rr * ld + kof + c4);
        }
        #pragma unroll
        for (int j = 0; j < (32 * NT) / 128; j++){
            int v = tid + 128 * j;
            Ws[v / NT][v % NT] = W[(kb + v / NT) * ldw + col0 + (v % NT)];
        }
        __syncthreads();
        #pragma unroll
        for (int kk = 0; kk < 32; kk += 4){
            float4 a[8];
            #pragma unroll
            for (int i = 0; i < 8; i++) a[i] = *(const float4*)&As[rows[i]][kk];
            #pragma unroll
            for (int u = 0; u < 4; u++){
                float w[CPT];
                #pragma unroll
                for (int c = 0; c < CPT; c++) w[c] = Ws[kk + u][cg * CPT + c];
                #pragma unroll
                for (int i = 0; i < 8; i++){
                    float av = (&a[i].x)[u];
                    #pragma unroll
                    for (int c = 0; c < CPT; c++) acc[i][c] = fmaf(av, w[c], acc[i][c]);
                }
            }
        }
    }
    #pragma unroll
    for (int c = 0; c < CPT; c++){
        int col = col0 + cg * CPT + c;
        float bv = bias[col];
        #pragma unroll
        for (int i = 0; i < 8; i++) C[rows[i] * ldc + col] = acc[i][c] + bv;
    }
}

// GRU GEMM: g_P = g_x @ W_gru + b_gru   (128 CTAs x 24 cols)
__global__ void __launch_bounds__(128) k_gemm_gru(
    const float* __restrict__ Wgru, const float* __restrict__ bgru)
{
    gemm_body<24>(g_x, 2048, 2048, (const float*)0, 0, 2048,
                  Wgru, 3072, bgru, g_P, 3072, blockIdx.x * 24);
}

// fused mid GEMMs: obs (64 CTAs) + selected-head img_out (64 CTAs)
__global__ void __launch_bounds__(128) k_gemm_mid(
    int t, const float* __restrict__ embed, const int* __restrict__ ensidx,
    const float* __restrict__ Woo, const float* __restrict__ boo,
    const float* __restrict__ Wio, const float* __restrict__ bio)
{
    if (blockIdx.x < 64){
        gemm_body<16>(g_deter, 1024, 1024, embed + (size_t)t * EMB_, T_ * EMB_, 2560,
                      Woo, 1024, boo, g_xo, 1024, blockIdx.x * 16);
    } else {
        int idx = ensidx[t];
        gemm_body<16>(g_deter, 1024, 1024, (const float*)0, 0, 1024,
                      Wio + (size_t)idx * 1024 * 1024, 1024,
                      bio + (size_t)idx * 1024, g_hs, 1024, (blockIdx.x - 64) * 16);
    }
}

// ---------------- k_gate: LN(3072) + GRU gates -> g_deter ----------------
__global__ void __launch_bounds__(256) k_gate(
    const float* __restrict__ ggru, const float* __restrict__ bngru)
{
    __shared__ float red[18];
    int row = blockIdx.x, tid = threadIdx.x;
    const float* P = &g_P[row * 3072];
    float v[12], s1 = 0.f, s2 = 0.f;
    #pragma unroll
    for (int j = 0; j < 12; j++){ v[j] = P[tid + 256 * j]; s1 += v[j]; s2 += v[j] * v[j]; }
    float2 r = blockred2(s1, s2, red);
    float mean = r.x * (1.f / 3072.f);
    float rstd = rstdf(r.y * (1.f / 3072.f) - mean * mean);
    #pragma unroll
    for (int j = 0; j < 4; j++){
        int h = tid + 256 * j;
        float lr = (v[j]     - mean) * rstd * ggru[h]        + bngru[h];
        float lc = (v[j + 4] - mean) * rstd * ggru[1024 + h] + bngru[1024 + h];
        float lu = (v[j + 8] - mean) * rstd * ggru[2048 + h] + bngru[2048 + h];
        float rr = sigf(lr);
        float cc = tanhf(rr * lc);
        float uu = sigf(lu - 1.f);                 // UPDATE_BIAS
        int di = row * DETER_ + h;
        g_deter[di] = uu * cc + (1.f - uu) * g_deter[di];
    }
}

// ---------------- k_post: LN+elu, dist heads, pack outputs ----------------
__global__ void __launch_bounds__(256) k_post(
    int t, const int* __restrict__ ensidx,
    const float* __restrict__ gio, const float* __restrict__ bnio,
    const float* __restrict__ Wid, const float* __restrict__ bid_,
    const float* __restrict__ goo, const float* __restrict__ bnoo,
    const float* __restrict__ Wod, const float* __restrict__ bod,
    float* __restrict__ out)
{
    __shared__ float hs_s[1024], xo_s[1024];
    __shared__ float psum[4][64];
    __shared__ float ds_s[64], od_s[64];
    __shared__ float red[18];
    int row = blockIdx.x, tid = threadIdx.x;
    int idx = ensidx[t];

    // LN + elu for hs (head-indexed scale/bias)
    {
        float a[4], s1 = 0.f, s2 = 0.f;
        #pragma unroll
        for (int j = 0; j < 4; j++){ a[j] = g_hs[row * HID_ + tid + 256 * j]; s1 += a[j]; s2 += a[j] * a[j]; }
        float2 r = blockred2(s1, s2, red);
        float mean = r.x * (1.f / 1024.f);
        float rstd = rstdf(r.y * (1.f / 1024.f) - mean * mean);
        #pragma unroll
        for (int j = 0; j < 4; j++){
            int h = tid + 256 * j;
            hs_s[h] = eluf((a[j] - mean) * rstd * gio[idx * HID_ + h] + bnio[idx * HID_ + h]);
        }
    }
    __syncthreads();
    // LN + elu for xo
    {
        float a[4], s1 = 0.f, s2 = 0.f;
        #pragma unroll
        for (int j = 0; j < 4; j++){ a[j] = g_xo[row * HID_ + tid + 256 * j]; s1 += a[j]; s2 += a[j] * a[j]; }
        float2 r = blockred2(s1, s2, red);
        float mean = r.x * (1.f / 1024.f);
        float rstd = rstdf(r.y * (1.f / 1024.f) - mean * mean);
        #pragma unroll
        for (int j = 0; j < 4; j++){
            int h = tid + 256 * j;
            xo_s[h] = eluf((a[j] - mean) * rstd * goo[h] + bnoo[h]);
        }
    }
    __syncthreads();

    // dist heads: 64 outputs each; lanes cover o contiguously (coalesced W reads)
    int o = tid & 63, p = tid >> 6;
    {
        const float* W = Wid + (size_t)idx * 1024 * 64;
        float s = 0.f;
        for (int k = p * 256; k < p * 256 + 256; k++) s = fmaf(hs_s[k], W[k * 64 + o], s);
        psum[p][o] = s;
    }
    __syncthreads();
    if (tid < 64) ds_s[tid] = psum[0][tid] + psum[1][tid] + psum[2][tid] + psum[3][tid] + bid_[idx * 64 + tid];
    __syncthreads();
    {
        float s = 0.f;
        for (int k = p * 256; k < p * 256 + 256; k++) s = fmaf(xo_s[k], Wod[k * 64 + o], s);
        psum[p][o] = s;
    }
    __syncthreads();
    if (tid < 64) od_s[tid] = psum[0][tid] + psum[1][tid] + psum[2][tid] + psum[3][tid] + bod[tid];
    __syncthreads();

    float* ob = out + ((size_t)row * T_ + t) * OUTW_;
    if (tid < 32){
        float om = od_s[tid], pm = ds_s[tid];
        ob[tid]       = om;   // omean
        ob[64 + tid]  = om;   // post_stoch
        ob[96 + tid]  = pm;   // pmean
        ob[160 + tid] = pm;   // prior_stoch
        g_stoch[row * STOCH_ + tid] = om;
    } else if (tid < 64){
        int oo = tid - 32;
        ob[32 + oo]  = splusf(od_s[tid]) + 0.1f;  // ostd
        ob[128 + oo] = splusf(ds_s[tid]) + 0.1f;  // pstd
    }
    #pragma unroll
    for (int j = 0; j < 4; j++){
        int h = tid + 256 * j;
        ob[192 + h] = g_deter[row * DETER_ + h];
    }
}

// ---------------- launch ----------------
extern "C" void kernel_launch(void* const* d_in, const int* in_sizes, int n_in,
                              void* d_out, int out_size)
{
    const float* embed  = (const float*)d_in[0];
    const float* action = (const float*)d_in[1];
    const void*  isf    = d_in[2];
    const int*   ensidx = (const int*)d_in[3];
    const float* Wii = (const float*)d_in[4],  *bii = (const float*)d_in[5];
    const float* gii = (const float*)d_in[6],  *bnii = (const float*)d_in[7];
    const float* Wgru = (const float*)d_in[8], *bgru = (const float*)d_in[9];
    const float* ggru = (const float*)d_in[10],*bngru = (const float*)d_in[11];
    const float* Wio = (const float*)d_in[12], *bio = (const float*)d_in[13];
    const float* gio = (const float*)d_in[14], *bnio = (const float*)d_in[15];
    const float* Wid = (const float*)d_in[16], *bid_ = (const float*)d_in[17];
    const float* Woo = (const float*)d_in[18], *boo = (const float*)d_in[19];
    const float* goo = (const float*)d_in[20], *bnoo = (const float*)d_in[21];
    const float* Wod = (const float*)d_in[22], *bod = (const float*)d_in[23];
    float* out = (float*)d_out;

    k_detect<<<1, 256>>>((const unsigned char*)isf);
    for (int t = 0; t < T_; t++){
        k_pre<<<B_, 256>>>(t, action, isf, Wii, bii, gii, bnii);
        k_gemm_gru<<<128, 128>>>(Wgru, bgru);
        k_gate<<<B_, 256>>>(ggru, bngru);
        k_gemm_mid<<<128, 128>>>(t, embed, ensidx, Woo, boo, Wio, bio);
        k_post<<<B_, 256>>>(t, ensidx, gio, bnio, Wid, bid_, goo, bnoo, Wod, bod, out);
    }
}

// round 4
// speedup vs baseline: 1.5585x; 1.5585x over previous
#include <cuda_runtime.h>
#include <math.h>

// ---------------- problem constants ----------------
#define B_     128
#define T_     64
#define EMB_   1536
#define ACT_   12
#define STOCH_ 32
#define DETER_ 1024
#define HID_   1024
#define OUTW_  1216   // 6*STOCH + DETER

typedef unsigned long long ull;

// ---------------- persistent device state ----------------
__device__ __align__(16) float g_x[B_ * 2048];     // GRU input rows: [x(1024) | deter_m(1024)]
__device__ __align__(16) float g_P[B_ * 3072];     // GRU pre-norm output
__device__ __align__(16) float g_deter[B_ * DETER_];
__device__ __align__(16) float g_stoch[B_ * STOCH_];
__device__ __align__(16) float g_hs[B_ * HID_];    // img_out pre-norm
__device__ __align__(16) float g_xo[B_ * HID_];    // obs_out pre-norm
__device__ int   g_mode;                           // 0=u8, 1=i32, 2=f32 for is_first

// ---------------- helpers ----------------
__device__ __forceinline__ float sigf(float x)  { return 1.f / (1.f + expf(-x)); }
__device__ __forceinline__ float splusf(float x){ return fmaxf(x, 0.f) + log1pf(expf(-fabsf(x))); }
__device__ __forceinline__ float eluf(float x)  { return x > 0.f ? x : expm1f(x); }
__device__ __forceinline__ float rstdf(float var){
    float a = var + 1e-5f;
    float r = rsqrtf(a);
    return r * (1.5f - 0.5f * a * r * r);   // one Newton step
}

__device__ __forceinline__ void fma2(ull &acc, ull a, ull b){
    asm("fma.rn.f32x2 %0, %1, %2, %0;" : "+l"(acc) : "l"(a), "l"(b));
}
__device__ __forceinline__ ull pk2(float x){
    ull r; asm("mov.b64 %0, {%1, %1};" : "=l"(r) : "f"(x)); return r;
}
__device__ __forceinline__ float2 up2(ull v){
    float2 f; asm("mov.b64 {%0, %1}, %2;" : "=f"(f.x), "=f"(f.y) : "l"(v)); return f;
}

__device__ __forceinline__ float get_mask(const void* isf, int row, int t){
    int e = row * T_ + t;
    int mode = g_mode;
    float f;
    if (mode == 0)      f = (float)((const unsigned char*)isf)[e];
    else if (mode == 1) f = (float)((const int*)isf)[e];
    else                f = ((const float*)isf)[e];
    return 1.f - f;
}

// block-wide (256 threads) sum of (a, b); sh must have >= 18 floats
__device__ __forceinline__ float2 blockred2(float a, float b, float* sh){
    #pragma unroll
    for (int o = 16; o; o >>= 1){
        a += __shfl_xor_sync(0xffffffffu, a, o);
        b += __shfl_xor_sync(0xffffffffu, b, o);
    }
    int w = threadIdx.x >> 5;
    if ((threadIdx.x & 31) == 0){ sh[w] = a; sh[8 + w] = b; }
    __syncthreads();
    if (threadIdx.x == 0){
        float sa = 0.f, sb = 0.f;
        #pragma unroll
        for (int i = 0; i < 8; i++){ sa += sh[i]; sb += sh[8 + i]; }
        sh[16] = sa; sh[17] = sb;
    }
    __syncthreads();
    return make_float2(sh[16], sh[17]);
}

// ---------------- dtype detector for is_first ----------------
__global__ void k_detect(const unsigned char* __restrict__ p){
    __shared__ int s[2];
    if (threadIdx.x < 2) s[threadIdx.x] = 0;
    __syncthreads();
    int f = 0, g = 0;
    for (int i = threadIdx.x; i < B_ * T_; i += blockDim.x){
        unsigned char b = p[i];
        if (b >= 2) f = 1;
        if (b == 1 && (i & 3)) g = 1;
    }
    if (f) atomicOr(&s[0], 1);
    if (g) atomicOr(&s[1], 1);
    __syncthreads();
    if (threadIdx.x == 0) g_mode = s[0] ? 2 : (s[1] ? 0 : 1);
}

// ---------------- k_pre: mask + img_in MLP + LN + elu -> g_x ----------------
__global__ void __launch_bounds__(256) k_pre(
    int t, const float* __restrict__ action, const void* __restrict__ isf,
    const float* __restrict__ Wii, const float* __restrict__ bii,
    const float* __restrict__ gii, const float* __restrict__ bnii)
{
    __shared__ float in44[44];
    __shared__ float red[18];
    int row = blockIdx.x, tid = threadIdx.x;
    float m = get_mask(isf, row, t);

    if (tid < 32)       in44[tid] = (t == 0 ? 0.f : g_stoch[row * STOCH_ + tid]) * m;
    else if (tid < 44)  in44[tid] = action[(row * T_ + t) * ACT_ + (tid - 32)] * m;
    __syncthreads();

    float acc[4];
    #pragma unroll
    for (int j = 0; j < 4; j++){
        int h = tid + 256 * j;
        float s = bii[h];
        #pragma unroll
        for (int k = 0; k < 44; k++) s = fmaf(in44[k], Wii[k * HID_ + h], s);
        acc[j] = s;
    }
    float s1 = 0.f, s2 = 0.f;
    #pragma unroll
    for (int j = 0; j < 4; j++){ s1 += acc[j]; s2 += acc[j] * acc[j]; }
    float2 r = blockred2(s1, s2, red);
    float mean = r.x * (1.f / 1024.f);
    float rstd = rstdf(r.y * (1.f / 1024.f) - mean * mean);

    #pragma unroll
    for (int j = 0; j < 4; j++){
        int h = tid + 256 * j;
        float xn = (acc[j] - mean) * rstd * gii[h] + bnii[h];
        g_x[row * 2048 + h] = eluf(xn);
        float dm = (t == 0 ? 0.f : g_deter[row * DETER_ + h]) * m;
        g_deter[row * DETER_ + h] = dm;          // masked old deter
        g_x[row * 2048 + 1024 + h] = dm;
    }
}

// ---------------- packed-f32x2 GEMM: C[128 x NT-tile] = A @ W + bias ----------------
// 256 threads, CTA tile 128 rows x NT cols. A is virtual concat A0(K0 cols)|A1.
// K % 32 == 0, K0 % 32 == 0. Thread (rg=tid>>3, cg=tid&7): rows 4*rg..4*rg+3 as two
// f32x2 row-pairs, cols col0 + cg + 8*c for c < NT/8. A staged k-major in smem
// (LDS.128 = 4 rows = 2 packed operands); W staged duplicated {w,w} in u64 smem.
// Register prefetch of next tile is issued before the compute phase.
template<int NT>
__device__ __forceinline__ void gemm256(
    const float* __restrict__ A0, int K0, int lda0,
    const float* __restrict__ A1, int lda1, int K,
    const float* __restrict__ W, int ldw, const float* __restrict__ bias,
    float* __restrict__ C, int ldc, int col0)
{
    constexpr int CPC = NT / 8;            // cols per thread
    constexpr int WE  = (32 * NT) / 256;   // W elems per thread per tile
    __shared__ float As[32][132];          // [k][row], padded
    __shared__ ull   Ws2[NT][34];          // [col][k] duplicated pairs, padded

    const int tid = threadIdx.x;
    const int cg = tid & 7, rg = tid >> 3;
    const int r_f = tid & 127, h_f = tid >> 7;   // fill: row, k-half

    ull acc[2][CPC];
    #pragma unroll
    for (int p = 0; p < 2; p++)
        #pragma unroll
        for (int c = 0; c < CPC; c++) acc[p][c] = 0ull;

    int wk[WE], wc[WE];
    #pragma unroll
    for (int i = 0; i < WE; i++){ int u = tid + 256 * i; wk[i] = u / NT; wc[i] = u % NT; }

    float4 pa[4];
    float  pw[WE];

    // prefetch tile kb=0
    {
        const float* Ap = (0 < K0) ? (A0 + r_f * lda0) : (A1 + r_f * lda1 - K0);
        #pragma unroll
        for (int i = 0; i < 4; i++) pa[i] = *(const float4*)(Ap + h_f * 16 + i * 4);
        #pragma unroll
        for (int i = 0; i < WE; i++) pw[i] = W[wk[i] * ldw + col0 + wc[i]];
    }

    for (int kb = 0; kb < K; kb += 32){
        __syncthreads();   // previous compute done
        #pragma unroll
        for (int i = 0; i < 4; i++){
            As[h_f * 16 + i * 4 + 0][r_f] = pa[i].x;
            As[h_f * 16 + i * 4 + 1][r_f] = pa[i].y;
            As[h_f * 16 + i * 4 + 2][r_f] = pa[i].z;
            As[h_f * 16 + i * 4 + 3][r_f] = pa[i].w;
        }
        #pragma unroll
        for (int i = 0; i < WE; i++) Ws2[wc[i]][wk[i]] = pk2(pw[i]);
        __syncthreads();   // tile visible

        int kn = kb + 32;
        if (kn < K){       // prefetch next tile (hidden under compute)
            const float* Ap = (kn < K0) ? (A0 + r_f * lda0 + kn) : (A1 + r_f * lda1 + (kn - K0));
            #pragma unroll
            for (int i = 0; i < 4; i++) pa[i] = *(const float4*)(Ap + h_f * 16 + i * 4);
            #pragma unroll
            for (int i = 0; i < WE; i++) pw[i] = W[(kn + wk[i]) * ldw + col0 + wc[i]];
        }

        #pragma unroll
        for (int kk = 0; kk < 32; kk += 4){
            ulonglong2 a0 = *(const ulonglong2*)&As[kk + 0][rg * 4];
            ulonglong2 a1 = *(const ulonglong2*)&As[kk + 1][rg * 4];
            ulonglong2 a2 = *(const ulonglong2*)&As[kk + 2][rg * 4];
            ulonglong2 a3 = *(const ulonglong2*)&As[kk + 3][rg * 4];
            #pragma unroll
            for (int c = 0; c < CPC; c++){
                const ull* wp = &Ws2[cg + 8 * c][kk];
                ulonglong2 w01 = *(const ulonglong2*)(wp);
                ulonglong2 w23 = *(const ulonglong2*)(wp + 2);
                fma2(acc[0][c], a0.x, w01.x); fma2(acc[1][c], a0.y, w01.x);
                fma2(acc[0][c], a1.x, w01.y); fma2(acc[1][c], a1.y, w01.y);
                fma2(acc[0][c], a2.x, w23.x); fma2(acc[1][c], a2.y, w23.x);
                fma2(acc[0][c], a3.x, w23.y); fma2(acc[1][c], a3.y, w23.y);
            }
        }
    }

    #pragma unroll
    for (int c = 0; c < CPC; c++){
        int col = col0 + cg + 8 * c;
        float bv = bias[col];
        #pragma unroll
        for (int p = 0; p < 2; p++){
            float2 v = up2(acc[p][c]);
            int row = rg * 4 + 2 * p;
            C[row * ldc + col]       = v.x + bv;
            C[(row + 1) * ldc + col] = v.y + bv;
        }
    }
}

// GRU GEMM: g_P = g_x @ W_gru + b_gru   (128 CTAs x 24 cols)
__global__ void __launch_bounds__(256) k_gemm_gru(
    const float* __restrict__ Wgru, const float* __restrict__ bgru)
{
    gemm256<24>(g_x, 2048, 2048, (const float*)0, 0, 2048,
                Wgru, 3072, bgru, g_P, 3072, blockIdx.x * 24);
}

// fused mid GEMMs: obs (64 CTAs, K=2560) + selected-head img_out (64 CTAs, K=1024)
__global__ void __launch_bounds__(256) k_gemm_mid(
    int t, const float* __restrict__ embed, const int* __restrict__ ensidx,
    const float* __restrict__ Woo, const float* __restrict__ boo,
    const float* __restrict__ Wio, const float* __restrict__ bio)
{
    if (blockIdx.x < 64){
        gemm256<16>(g_deter, 1024, 1024, embed + (size_t)t * EMB_, T_ * EMB_, 2560,
                    Woo, 1024, boo, g_xo, 1024, blockIdx.x * 16);
    } else {
        int idx = ensidx[t];
        gemm256<16>(g_deter, 1024, 1024, (const float*)0, 0, 1024,
                    Wio + (size_t)idx * 1024 * 1024, 1024,
                    bio + (size_t)idx * 1024, g_hs, 1024, (blockIdx.x - 64) * 16);
    }
}

// ---------------- k_gate: LN(3072) + GRU gates -> g_deter ----------------
__global__ void __launch_bounds__(256) k_gate(
    const float* __restrict__ ggru, const float* __restrict__ bngru)
{
    __shared__ float red[18];
    int row = blockIdx.x, tid = threadIdx.x;
    const float* P = &g_P[row * 3072];
    float v[12], s1 = 0.f, s2 = 0.f;
    #pragma unroll
    for (int j = 0; j < 12; j++){ v[j] = P[tid + 256 * j]; s1 += v[j]; s2 += v[j] * v[j]; }
    float2 r = blockred2(s1, s2, red);
    float mean = r.x * (1.f / 3072.f);
    float rstd = rstdf(r.y * (1.f / 3072.f) - mean * mean);
    #pragma unroll
    for (int j = 0; j < 4; j++){
        int h = tid + 256 * j;
        float lr = (v[j]     - mean) * rstd * ggru[h]        + bngru[h];
        float lc = (v[j + 4] - mean) * rstd * ggru[1024 + h] + bngru[1024 + h];
        float lu = (v[j + 8] - mean) * rstd * ggru[2048 + h] + bngru[2048 + h];
        float rr = sigf(lr);
        float cc = tanhf(rr * lc);
        float uu = sigf(lu - 1.f);                 // UPDATE_BIAS
        int di = row * DETER_ + h;
        g_deter[di] = uu * cc + (1.f - uu) * g_deter[di];
    }
}

// ---------------- k_post: LN+elu, dist heads, pack outputs ----------------
__global__ void __launch_bounds__(256) k_post(
    int t, const int* __restrict__ ensidx,
    const float* __restrict__ gio, const float* __restrict__ bnio,
    const float* __restrict__ Wid, const float* __restrict__ bid_,
    const float* __restrict__ goo, const float* __restrict__ bnoo,
    const float* __restrict__ Wod, const float* __restrict__ bod,
    float* __restrict__ out)
{
    __shared__ float hs_s[1024], xo_s[1024];
    __shared__ float psum[4][64];
    __shared__ float ds_s[64], od_s[64];
    __shared__ float red[18];
    int row = blockIdx.x, tid = threadIdx.x;
    int idx = ensidx[t];

    {
        float a[4], s1 = 0.f, s2 = 0.f;
        #pragma unroll
        for (int j = 0; j < 4; j++){ a[j] = g_hs[row * HID_ + tid + 256 * j]; s1 += a[j]; s2 += a[j] * a[j]; }
        float2 r = blockred2(s1, s2, red);
        float mean = r.x * (1.f / 1024.f);
        float rstd = rstdf(r.y * (1.f / 1024.f) - mean * mean);
        #pragma unroll
        for (int j = 0; j < 4; j++){
            int h = tid + 256 * j;
            hs_s[h] = eluf((a[j] - mean) * rstd * gio[idx * HID_ + h] + bnio[idx * HID_ + h]);
        }
    }
    __syncthreads();
    {
        float a[4], s1 = 0.f, s2 = 0.f;
        #pragma unroll
        for (int j = 0; j < 4; j++){ a[j] = g_xo[row * HID_ + tid + 256 * j]; s1 += a[j]; s2 += a[j] * a[j]; }
        float2 r = blockred2(s1, s2, red);
        float mean = r.x * (1.f / 1024.f);
        float rstd = rstdf(r.y * (1.f / 1024.f) - mean * mean);
        #pragma unroll
        for (int j = 0; j < 4; j++){
            int h = tid + 256 * j;
            xo_s[h] = eluf((a[j] - mean) * rstd * goo[h] + bnoo[h]);
        }
    }
    __syncthreads();

    int o = tid & 63, p = tid >> 6;
    {
        const float* W = Wid + (size_t)idx * 1024 * 64;
        float s = 0.f;
        for (int k = p * 256; k < p * 256 + 256; k++) s = fmaf(hs_s[k], W[k * 64 + o], s);
        psum[p][o] = s;
    }
    __syncthreads();
    if (tid < 64) ds_s[tid] = psum[0][tid] + psum[1][tid] + psum[2][tid] + psum[3][tid] + bid_[idx * 64 + tid];
    __syncthreads();
    {
        float s = 0.f;
        for (int k = p * 256; k < p * 256 + 256; k++) s = fmaf(xo_s[k], Wod[k * 64 + o], s);
        psum[p][o] = s;
    }
    __syncthreads();
    if (tid < 64) od_s[tid] = psum[0][tid] + psum[1][tid] + psum[2][tid] + psum[3][tid] + bod[tid];
    __syncthreads();

    float* ob = out + ((size_t)row * T_ + t) * OUTW_;
    if (tid < 32){
        float om = od_s[tid], pm = ds_s[tid];
        ob[tid]       = om;   // omean
        ob[64 + tid]  = om;   // post_stoch
        ob[96 + tid]  = pm;   // pmean
        ob[160 + tid] = pm;   // prior_stoch
        g_stoch[row * STOCH_ + tid] = om;
    } else if (tid < 64){
        int oo = tid - 32;
        ob[32 + oo]  = splusf(od_s[tid]) + 0.1f;  // ostd
        ob[128 + oo] = splusf(ds_s[tid]) + 0.1f;  // pstd
    }
    #pragma unroll
    for (int j = 0; j < 4; j++){
        int h = tid + 256 * j;
        ob[192 + h] = g_deter[row * DETER_ + h];
    }
}

// ---------------- launch ----------------
extern "C" void kernel_launch(void* const* d_in, const int* in_sizes, int n_in,
                              void* d_out, int out_size)
{
    const float* embed  = (const float*)d_in[0];
    const float* action = (const float*)d_in[1];
    const void*  isf    = d_in[2];
    const int*   ensidx = (const int*)d_in[3];
    const float* Wii = (const float*)d_in[4],  *bii = (const float*)d_in[5];
    const float* gii = (const float*)d_in[6],  *bnii = (const float*)d_in[7];
    const float* Wgru = (const float*)d_in[8], *bgru = (const float*)d_in[9];
    const float* ggru = (const float*)d_in[10],*bngru = (const float*)d_in[11];
    const float* Wio = (const float*)d_in[12], *bio = (const float*)d_in[13];
    const float* gio = (const float*)d_in[14], *bnio = (const float*)d_in[15];
    const float* Wid = (const float*)d_in[16], *bid_ = (const float*)d_in[17];
    const float* Woo = (const float*)d_in[18], *boo = (const float*)d_in[19];
    const float* goo = (const float*)d_in[20], *bnoo = (const float*)d_in[21];
    const float* Wod = (const float*)d_in[22], *bod = (const float*)d_in[23];
    float* out = (float*)d_out;

    k_detect<<<1, 256>>>((const unsigned char*)isf);
    for (int t = 0; t < T_; t++){
        k_pre<<<B_, 256>>>(t, action, isf, Wii, bii, gii, bnii);
        k_gemm_gru<<<128, 256>>>(Wgru, bgru);
        k_gate<<<B_, 256>>>(ggru, bngru);
        k_gemm_mid<<<128, 256>>>(t, embed, ensidx, Woo, boo, Wio, bio);
        k_post<<<B_, 256>>>(t, ensidx, gio, bnio, Wid, bid_, goo, bnoo, Wod, bod, out);
    }
}